// round 13
// baseline (speedup 1.0000x reference)
#include <cuda_runtime.h>
#include <cuda_bf16.h>
#include <cuda_fp16.h>
#include <stdint.h>
#include <cstdint>
#include <math.h>

// Problem constants
#define NB 16        // B = b*h
#define TLEN 4096    // sequence length
#define NHASH 8
#define NBUCK 64     // local buckets per round
#define NGBUCK 512   // global buckets per B-row
#define CHUNKS 512   // chunks per B-row
#define CS 64        // chunk size
#define E 64         // head dim
#define STR 68       // smem row stride (floats) for hash kernel

typedef unsigned int u32;

// Scratch (device globals — no allocations allowed)
__device__ unsigned char g_buckets[NB * NHASH * TLEN];
__device__ int    g_counts [NB * NGBUCK];
__device__ int    g_offsets[NB * NGBUCK];
__device__ int    g_st     [NB * NHASH * TLEN];
__device__ float  g_logits [NB * NHASH * TLEN];
__device__ __half g_o      [(size_t)NB * NHASH * TLEN * E];   // 64MB (fp16 per-round outputs)

__global__ void zero_counts_kernel(int Boff) {
    int i = blockIdx.x * blockDim.x + threadIdx.x;
    g_counts[Boff * NGBUCK + i] = 0;
}

// ---------------- hash: warp = one hash round, rotations in registers ----------------
__global__ void __launch_bounds__(256, 2) hash_kernel(const float* __restrict__ qk,
                                                      const float* __restrict__ rot,
                                                      int Boff) {
    extern __shared__ float hsm[];
    float* sq = hsm;                 // 64 tokens x STR

    int tid = threadIdx.x;
    int B  = (blockIdx.x >> 6) + Boff;
    int t0 = (blockIdx.x & 63) << 6;
    int b = B >> 3, hh = B & 7;

    // Stage 64 query rows (coalesced float4)
    for (int idx = tid; idx < 64 * 16; idx += 256) {
        int tok = idx >> 4, e4 = (idx & 15) << 2;
        const float* q = qk + (((size_t)(b * TLEN + t0 + tok)) * 8 + hh) * E;
        *(float4*)&sq[tok * STR + e4] = *(const float4*)&q[e4];
    }

    int w = tid >> 5, lane = tid & 31;
    int nh = w;                      // warp <-> hash round

    // This warp's 32 rotation columns, all 64 e-values, into registers.
    // rot[e*256 + nh*32 + lane]: per-e the warp reads 128B contiguous.
    float rv[64];
    #pragma unroll
    for (int e = 0; e < 64; e++) rv[e] = rot[e * 256 + nh * 32 + lane];

    __syncthreads();

    for (int r0 = 0; r0 < 64; r0 += 4) {
        float a0[4], a1[4];
        #pragma unroll
        for (int r = 0; r < 4; r++) { a0[r] = 0.f; a1[r] = 0.f; }

        #pragma unroll
        for (int e4 = 0; e4 < 64; e4 += 8) {
            #pragma unroll
            for (int r = 0; r < 4; r++) {
                float4 qa = *(const float4*)&sq[(r0 + r) * STR + e4];
                float4 qb = *(const float4*)&sq[(r0 + r) * STR + e4 + 4];
                a0[r] = fmaf(qa.x, rv[e4],     fmaf(qa.y, rv[e4 + 1],
                        fmaf(qa.z, rv[e4 + 2], fmaf(qa.w, rv[e4 + 3], a0[r]))));
                a1[r] = fmaf(qb.x, rv[e4 + 4], fmaf(qb.y, rv[e4 + 5],
                        fmaf(qb.z, rv[e4 + 6], fmaf(qb.w, rv[e4 + 7], a1[r]))));
            }
        }

        #pragma unroll
        for (int r = 0; r < 4; r++) {
            float a = a0[r] + a1[r];
            // candidates (a, lane) and (-a, lane+32); jnp.argmax = first max
            float bestv; int besti;
            if (-a > a) { bestv = -a; besti = lane + 32; }
            else        { bestv =  a; besti = lane; }
            #pragma unroll
            for (int off = 16; off; off >>= 1) {
                float ov = __shfl_down_sync(0xffffffffu, bestv, off);
                int   oi = __shfl_down_sync(0xffffffffu, besti, off);
                if (ov > bestv || (ov == bestv && oi < besti)) { bestv = ov; besti = oi; }
            }
            besti = __shfl_sync(0xffffffffu, besti, 0);
            if (lane == 0) {
                int t = t0 + r0 + r;
                g_buckets[(B * NHASH + nh) * TLEN + t] = (unsigned char)besti;
                atomicAdd(&g_counts[B * NGBUCK + nh * NBUCK + besti], 1);
            }
        }
    }
}

__global__ void scan_kernel(int Boff) {
    __shared__ int s[NGBUCK];
    int B = blockIdx.x + Boff, tid = threadIdx.x;
    s[tid] = g_counts[B * NGBUCK + tid];
    __syncthreads();
    for (int off = 1; off < NGBUCK; off <<= 1) {
        int v = (tid >= off) ? s[tid - off] : 0;
        __syncthreads();
        s[tid] += v;
        __syncthreads();
    }
    g_offsets[B * NGBUCK + tid] = tid ? s[tid - 1] : 0;
}

// Stable counting-sort scatter (R10 known-good shape): 256 threads, 16 passes.
__global__ void scatter_kernel(int Boff) {
    int B = (blockIdx.x >> 3) + Boff, nh = blockIdx.x & 7;
    __shared__ int cnt[NBUCK];
    __shared__ int wcnt[8][NBUCK];
    int tid = threadIdx.x, w = tid >> 5, lane = tid & 31;

    if (tid < NBUCK) cnt[tid] = g_offsets[B * NGBUCK + nh * NBUCK + tid];
    const unsigned char* src = &g_buckets[(B * NHASH + nh) * TLEN];
    int* dst = &g_st[B * (NHASH * TLEN)];

    for (int pass = 0; pass < 16; pass++) {
        wcnt[w][lane] = 0; wcnt[w][lane + 32] = 0;
        __syncthreads();
        int t = pass * 256 + tid;
        int bk = src[t];
        unsigned mask = __match_any_sync(0xffffffffu, bk);
        int rank = __popc(mask & ((1u << lane) - 1u));
        if (rank == 0) wcnt[w][bk] = __popc(mask);
        __syncthreads();
        int pos = cnt[bk] + rank;
        #pragma unroll
        for (int w2 = 0; w2 < 8; w2++)
            if (w2 < w) pos += wcnt[w2][bk];
        dst[pos] = t;
        __syncthreads();
        if (tid < NBUCK) {
            int s = 0;
            #pragma unroll
            for (int w2 = 0; w2 < 8; w2++) s += wcnt[w2][tid];
            cnt[tid] += s;
        }
        __syncthreads();
    }
}

// ---------------- helpers ----------------
__device__ __forceinline__ u32 swz(int row, int chunk) {
    return (u32)(row * 128 + (((chunk ^ (row & 7)) & 7) << 4));
}
__device__ __forceinline__ void ldsm_x4(u32* r, u32 addr) {
    asm volatile("ldmatrix.sync.aligned.m8n8.x4.shared.b16 {%0,%1,%2,%3}, [%4];"
                 : "=r"(r[0]), "=r"(r[1]), "=r"(r[2]), "=r"(r[3]) : "r"(addr));
}
__device__ __forceinline__ void ldsm_x4t(u32* r, u32 addr) {
    asm volatile("ldmatrix.sync.aligned.m8n8.x4.trans.shared.b16 {%0,%1,%2,%3}, [%4];"
                 : "=r"(r[0]), "=r"(r[1]), "=r"(r[2]), "=r"(r[3]) : "r"(addr));
}
__device__ __forceinline__ void mma_bf16(float* d, const u32* a, u32 b0, u32 b1) {
    asm volatile("mma.sync.aligned.m16n8k16.row.col.f32.bf16.bf16.f32 "
                 "{%0,%1,%2,%3},{%4,%5,%6,%7},{%8,%9},{%0,%1,%2,%3};"
                 : "+f"(d[0]), "+f"(d[1]), "+f"(d[2]), "+f"(d[3])
                 : "r"(a[0]), "r"(a[1]), "r"(a[2]), "r"(a[3]), "r"(b0), "r"(b1));
}
__device__ __forceinline__ u32 prmt7632(u32 a, u32 b) {
    u32 r;
    asm("prmt.b32 %0, %1, %2, 0x7632;" : "=r"(r) : "r"(a), "r"(b));
    return r;
}
// Veltkamp truncation split: hi = trunc-bf16(x) (exact residual), lo = bf16(x-hi)
__device__ __forceinline__ void split2(float a, float b, u32& hi, u32& lo) {
    u32 ua = __float_as_uint(a) & 0xFFFF0000u;
    u32 ub = __float_as_uint(b) & 0xFFFF0000u;
    hi = prmt7632(ua, ub);
    float la = a - __uint_as_float(ua);
    float lb = b - __uint_as_float(ub);
    lo = prmt7632(__float_as_uint(la), __float_as_uint(lb));
}
__device__ __forceinline__ void split8v(const float* x, uint4& hi, uint4& lo) {
    u32 h[4], l[4];
    #pragma unroll
    for (int p = 0; p < 4; p++) split2(x[2*p], x[2*p+1], h[p], l[p]);
    hi = make_uint4(h[0], h[1], h[2], h[3]);
    lo = make_uint4(l[0], l[1], l[2], l[3]);
}

// ---------------- tensor-core attention ----------------
#define SM_KLO 16384
#define SM_VHI 32768
#define SM_VLO 49152
#define SM_PO  65536
#define SM_INV 82944
#define SM_RDS 83456
#define SM_STK 83968
#define ATTN_SMEM 84480
#define POSTR 68

__global__ void __launch_bounds__(256, 2) attn_kernel(const float* __restrict__ qk,
                                                      const float* __restrict__ vv,
                                                      int Boff) {
    extern __shared__ char smem[];
    float* po   = (float*)(smem + SM_PO);
    float* invn = (float*)(smem + SM_INV);
    float* reds = (float*)(smem + SM_RDS);
    int*   stk  = (int*)  (smem + SM_STK);

    int tid = threadIdx.x;
    int Bq = (blockIdx.x >> 9) + Boff;
    int c  = blockIdx.x & (CHUNKS - 1);
    int cp = (c + CHUNKS - 1) & (CHUNKS - 1);
    int b = Bq >> 3, hh = Bq & 7;
    int nh = c >> 6;

    // ---- gather (L2-resident inputs) + truncation split + key norms ----
    {
        int seg = tid & 7;              // 8-col segment of a row
        const int* stsrc = &g_st[Bq * (NHASH * TLEN)];
        #pragma unroll
        for (int pass = 0; pass < 4; pass++) {
            int j = (tid >> 3) + pass * 32;
            int p = (j < 64) ? (c * CS + j) : (cp * CS + j - 64);
            int tj = stsrc[p];
            size_t base = (((size_t)(b * TLEN + tj)) * 8 + hh) * E + seg * 8;
            float x[8], y[8];
            *(float4*)&x[0] = *(const float4*)&qk[base];
            *(float4*)&x[4] = *(const float4*)&qk[base + 4];
            *(float4*)&y[0] = *(const float4*)&vv[base];
            *(float4*)&y[4] = *(const float4*)&vv[base + 4];
            u32 off = swz(j, seg);

            uint4 hi, lo;
            split8v(x, hi, lo);
            *(uint4*)(smem + off)          = hi;
            *(uint4*)(smem + SM_KLO + off) = lo;
            split8v(y, hi, lo);
            *(uint4*)(smem + SM_VHI + off) = hi;
            *(uint4*)(smem + SM_VLO + off) = lo;

            float ss = 0.f;
            #pragma unroll
            for (int i = 0; i < 8; i++) ss = fmaf(x[i], x[i], ss);
            ss += __shfl_xor_sync(0xffffffffu, ss, 1);
            ss += __shfl_xor_sync(0xffffffffu, ss, 2);
            ss += __shfl_xor_sync(0xffffffffu, ss, 4);
            if (seg == 0) {
                stk[j] = tj;
                invn[j] = 1.f / fmaxf(sqrtf(ss), 1e-12f);
            }
        }
    }
    __syncthreads();

    int w = tid >> 5, lane = tid & 31;
    int wm = w & 3, wn = w >> 2;
    int m0 = wm * 16, n0 = wn * 64;
    int g  = lane >> 3, lr = lane & 7;
    u32 kb = (u32)__cvta_generic_to_shared(smem);

    // ---- QK: D[64q,128k] via 3 split MMAs ----
    float acc[8][4];
    #pragma unroll
    for (int nt = 0; nt < 8; nt++) { acc[nt][0]=0.f; acc[nt][1]=0.f; acc[nt][2]=0.f; acc[nt][3]=0.f; }

    #pragma unroll
    for (int ck = 0; ck < 4; ck++) {
        int arow = m0 + ((g & 1) << 3) + lr;
        u32 aoff = swz(arow, 2 * ck + (g >> 1));
        u32 aH[4], aL[4];
        ldsm_x4(aH, kb + aoff);
        ldsm_x4(aL, kb + SM_KLO + aoff);
        #pragma unroll
        for (int p = 0; p < 4; p++) {
            int brow = n0 + 16 * p + ((g >> 1) << 3) + lr;
            u32 boff = swz(brow, 2 * ck + (g & 1));
            u32 bH[4], bL[4];
            ldsm_x4(bH, kb + boff);
            ldsm_x4(bL, kb + SM_KLO + boff);
            mma_bf16(acc[2*p],   aH, bH[0], bH[1]);
            mma_bf16(acc[2*p+1], aH, bH[2], bH[3]);
            mma_bf16(acc[2*p],   aH, bL[0], bL[1]);
            mma_bf16(acc[2*p+1], aH, bL[2], bL[3]);
            mma_bf16(acc[2*p],   aL, bH[0], bH[1]);
            mma_bf16(acc[2*p+1], aL, bH[2], bH[3]);
        }
    }

    // ---- scale by key inv-norm, self-mask, bound-max softmax ----
    int rA = m0 + (lane >> 2), rB = rA + 8;
    int tiA = stk[rA], tiB = stk[rB];
    float mA = 1.0f / invn[rA];
    float mB = 1.0f / invn[rB];

    float sA = 0.f, sB = 0.f;
    #pragma unroll
    for (int nt = 0; nt < 8; nt++) {
        int c0 = n0 + 8 * nt + 2 * (lane & 3);
        float i0 = invn[c0], i1 = invn[c0 + 1];
        int tc0 = stk[c0], tc1 = stk[c0 + 1];
        float d0 = acc[nt][0] * i0, d1 = acc[nt][1] * i1;
        float d2 = acc[nt][2] * i0, d3 = acc[nt][3] * i1;
        if (tc0 == tiA) d0 = -50000.f;
        if (tc1 == tiA) d1 = -50000.f;
        if (tc0 == tiB) d2 = -50000.f;
        if (tc1 == tiB) d3 = -50000.f;
        acc[nt][0] = __expf(d0 - mA);
        acc[nt][1] = __expf(d1 - mA);
        acc[nt][2] = __expf(d2 - mB);
        acc[nt][3] = __expf(d3 - mB);
        sA += acc[nt][0] + acc[nt][1];
        sB += acc[nt][2] + acc[nt][3];
    }
    sA += __shfl_xor_sync(0xffffffffu, sA, 1);
    sA += __shfl_xor_sync(0xffffffffu, sA, 2);
    sB += __shfl_xor_sync(0xffffffffu, sB, 1);
    sB += __shfl_xor_sync(0xffffffffu, sB, 2);

    int ridx = (wm * 2 + wn) * 16 + (lane >> 2);
    int pidx = (wm * 2 + (1 - wn)) * 16 + (lane >> 2);
    if ((lane & 3) == 0) { reds[ridx] = sA; reds[ridx + 8] = sB; }
    __syncthreads();
    sA += reds[pidx]; sB += reds[pidx + 8];
    float invsA = 1.f / sA, invsB = 1.f / sB;
    float lseA = mA + __logf(sA), lseB = mB + __logf(sB);

    // ---- P -> bf16 hi/lo fragments via truncation split ----
    u32 phA[8], phB[8], plA[8], plB[8];
    #pragma unroll
    for (int nt = 0; nt < 8; nt++) {
        split2(acc[nt][0], acc[nt][1], phA[nt], plA[nt]);
        split2(acc[nt][2], acc[nt][3], phB[nt], plB[nt]);
    }

    // ---- PV: out[64q,64d] partials over this warp's 64 j's ----
    float av[8][4];
    #pragma unroll
    for (int nt = 0; nt < 8; nt++) { av[nt][0]=0.f; av[nt][1]=0.f; av[nt][2]=0.f; av[nt][3]=0.f; }

    #pragma unroll
    for (int k = 0; k < 4; k++) {
        u32 aH[4] = { phA[2*k], phB[2*k], phA[2*k+1], phB[2*k+1] };
        u32 aL[4] = { plA[2*k], plB[2*k], plA[2*k+1], plB[2*k+1] };
        int vrow = n0 + 16 * k + ((g & 1) << 3) + lr;
        #pragma unroll
        for (int p = 0; p < 4; p++) {
            u32 voff = swz(vrow, 2 * p + (g >> 1));
            u32 bH[4], bL[4];
            ldsm_x4t(bH, kb + SM_VHI + voff);
            ldsm_x4t(bL, kb + SM_VLO + voff);
            mma_bf16(av[2*p],   aH, bH[0], bH[1]);
            mma_bf16(av[2*p+1], aH, bH[2], bH[3]);
            mma_bf16(av[2*p],   aH, bL[0], bL[1]);
            mma_bf16(av[2*p+1], aH, bL[2], bL[3]);
            mma_bf16(av[2*p],   aL, bH[0], bH[1]);
            mma_bf16(av[2*p+1], aL, bH[2], bH[3]);
        }
    }

    // ---- combine warp-pair partials; direct fp16 store ----
    if (wn == 1) {
        #pragma unroll
        for (int nt = 0; nt < 8; nt++) {
            int c0 = 8 * nt + 2 * (lane & 3);
            po[rA * POSTR + c0]     = av[nt][0];
            po[rA * POSTR + c0 + 1] = av[nt][1];
            po[rB * POSTR + c0]     = av[nt][2];
            po[rB * POSTR + c0 + 1] = av[nt][3];
        }
    }
    __syncthreads();
    if (wn == 0) {
        size_t orowA = ((size_t)((Bq * NHASH + nh) * TLEN + tiA)) * E;
        size_t orowB = ((size_t)((Bq * NHASH + nh) * TLEN + tiB)) * E;
        #pragma unroll
        for (int nt = 0; nt < 8; nt++) {
            int c0 = 8 * nt + 2 * (lane & 3);
            float o0 = (av[nt][0] + po[rA * POSTR + c0])     * invsA;
            float o1 = (av[nt][1] + po[rA * POSTR + c0 + 1]) * invsA;
            float o2 = (av[nt][2] + po[rB * POSTR + c0])     * invsB;
            float o3 = (av[nt][3] + po[rB * POSTR + c0 + 1]) * invsB;
            __half2 hA = __floats2half2_rn(o0, o1);
            __half2 hB = __floats2half2_rn(o2, o3);
            *(u32*)&g_o[orowA + c0] = *(u32*)&hA;
            *(u32*)&g_o[orowB + c0] = *(u32*)&hB;
        }
        if ((lane & 3) == 0) {
            g_logits[(Bq * NHASH + nh) * TLEN + tiA] = lseA;
            g_logits[(Bq * NHASH + nh) * TLEN + tiB] = lseB;
        }
    }
}

// ---------------- combine ----------------
// Block = 16 tokens x 16 dim-groups. Logits staged once through smem.
__global__ void combine_kernel(float* __restrict__ out) {
    __shared__ float sl[16][NHASH];
    int tid = threadIdx.x;
    int tok0 = blockIdx.x * 16;

    if (tid < 128) {
        int tk = tid >> 3, nh = tid & 7;
        int token = tok0 + tk;
        int B = token >> 12, t = token & (TLEN - 1);
        sl[tk][nh] = g_logits[(B * NHASH + nh) * TLEN + t];
    }
    __syncthreads();

    int tk = tid >> 4;
    int d4 = (tid & 15) << 2;
    int token = tok0 + tk;
    int B = token >> 12, t = token & (TLEN - 1);

    float l[NHASH];
    float mx = -INFINITY;
    #pragma unroll
    for (int nh = 0; nh < NHASH; nh++) {
        l[nh] = sl[tk][nh];
        mx = fmaxf(mx, l[nh]);
    }
    float s = 0.f;
    #pragma unroll
    for (int nh = 0; nh < NHASH; nh++) { l[nh] = __expf(l[nh] - mx); s += l[nh]; }
    float inv = 1.f / s;
    float4 acc = make_float4(0.f, 0.f, 0.f, 0.f);
    #pragma unroll
    for (int nh = 0; nh < NHASH; nh++) {
        float wgt = l[nh] * inv;
        uint2 raw = *(const uint2*)&g_o[((size_t)((B * NHASH + nh) * TLEN + t)) * E + d4];
        float2 f01 = __half22float2(*(__half2*)&raw.x);
        float2 f23 = __half22float2(*(__half2*)&raw.y);
        acc.x = fmaf(wgt, f01.x, acc.x);
        acc.y = fmaf(wgt, f01.y, acc.y);
        acc.z = fmaf(wgt, f23.x, acc.z);
        acc.w = fmaf(wgt, f23.y, acc.w);
    }
    *(float4*)&out[((size_t)token) * E + d4] = acc;
}

extern "C" void kernel_launch(void* const* d_in, const int* in_sizes, int n_in,
                              void* d_out, int out_size) {
    const float* qk  = (const float*)d_in[0];
    // d_in[1] = k is unused by the reference (shared-QK attention)
    const float* v   = (const float*)d_in[2];
    const float* rot = (const float*)d_in[3];
    float* out = (float*)d_out;

    const int hash_smem = 64 * STR * (int)sizeof(float);   // 17408
    cudaFuncSetAttribute(attn_kernel, cudaFuncAttributeMaxDynamicSharedMemorySize, ATTN_SMEM);
    cudaFuncSetAttribute(hash_kernel, cudaFuncAttributeMaxDynamicSharedMemorySize, hash_smem);

    cudaStream_t s2 = 0;
    cudaEvent_t eF = 0, eJ = 0;
    bool forked = false;
    {
        cudaStream_t tmp;
        if (cudaStreamCreateWithFlags(&tmp, cudaStreamNonBlocking) == cudaSuccess) {
            if (cudaEventCreateWithFlags(&eF, cudaEventDisableTiming) == cudaSuccess &&
                cudaEventCreateWithFlags(&eJ, cudaEventDisableTiming) == cudaSuccess) {
                s2 = tmp;
                forked = true;
            }
        }
    }
    cudaStream_t sB = forked ? s2 : (cudaStream_t)0;

    // Fork: the side stream must wait on an event recorded in the captured
    // origin stream to become part of the capture graph.
    zero_counts_kernel<<<16, 256, 0, 0>>>(0);
    if (forked) {
        cudaEventRecord(eF, 0);
        cudaStreamWaitEvent(s2, eF, 0);
    }

    // Half A chain (legacy stream) / Half B chain (side stream)
    zero_counts_kernel<<<16, 256, 0, sB>>>(NB / 2);
    hash_kernel   <<<(NB / 2) * 64,     256, hash_smem, 0 >>>(qk, rot, 0);
    hash_kernel   <<<(NB / 2) * 64,     256, hash_smem, sB>>>(qk, rot, NB / 2);
    scan_kernel   <<<NB / 2,            NGBUCK, 0,      0 >>>(0);
    scatter_kernel<<<(NB / 2) * NHASH,  256, 0,         0 >>>(0);
    attn_kernel   <<<(NB / 2) * CHUNKS, 256, ATTN_SMEM, 0 >>>(qk, v, 0);
    scan_kernel   <<<NB / 2,            NGBUCK, 0,      sB>>>(NB / 2);
    scatter_kernel<<<(NB / 2) * NHASH,  256, 0,         sB>>>(NB / 2);
    attn_kernel   <<<(NB / 2) * CHUNKS, 256, ATTN_SMEM, sB>>>(qk, v, NB / 2);

    if (forked) {
        cudaEventRecord(eJ, s2);
        cudaStreamWaitEvent(0, eJ, 0);
    }
    combine_kernel<<<NB * TLEN / 16, 256>>>(out);
}

// round 14
// speedup vs baseline: 1.4881x; 1.4881x over previous
#include <cuda_runtime.h>
#include <cuda_bf16.h>
#include <cuda_fp16.h>
#include <stdint.h>
#include <cstdint>
#include <math.h>

// Problem constants
#define NB 16        // B = b*h
#define TLEN 4096    // sequence length
#define NHASH 8
#define NBUCK 64     // local buckets per round
#define NGBUCK 512   // global buckets per B-row
#define CHUNKS 512   // chunks per B-row
#define CS 64        // chunk size
#define E 64         // head dim
#define STR 68       // smem row stride (floats) for hash kernel

typedef unsigned int u32;

// Scratch (device globals — no allocations allowed)
__device__ unsigned char g_buckets[NB * NHASH * TLEN];
__device__ int    g_counts [NB * NGBUCK];
__device__ int    g_offsets[NB * NGBUCK];
__device__ int    g_st     [NB * NHASH * TLEN];
__device__ float  g_logits [NB * NHASH * TLEN];
__device__ __half g_o      [(size_t)NB * NHASH * TLEN * E];   // 64MB (fp16 per-round outputs)

__global__ void zero_counts_kernel(int Boff) {
    int i = blockIdx.x * blockDim.x + threadIdx.x;
    g_counts[Boff * NGBUCK + i] = 0;
}

// ---------------- hash (R10 structure; nh processed in PAIRS to reuse q-loads) ----------------
__global__ void __launch_bounds__(256, 2) hash_kernel(const float* __restrict__ qk,
                                                      const float* __restrict__ rot,
                                                      int Boff) {
    extern __shared__ float hsm[];
    float* srot = hsm;               // 256 rows x STR
    float* sq   = srot + 256 * STR;  // 64 tokens x STR

    int tid = threadIdx.x;
    int B  = (blockIdx.x >> 6) + Boff;
    int t0 = (blockIdx.x & 63) << 6;
    int b = B >> 3, hh = B & 7;

    for (int idx = tid; idx < 64 * NHASH * 32; idx += 256) {
        int e = idx >> 8, r = idx & 255;
        srot[r * STR + e] = rot[idx];
    }
    for (int idx = tid; idx < 64 * 16; idx += 256) {
        int tok = idx >> 4, e4 = (idx & 15) << 2;
        const float* q = qk + (((size_t)(b * TLEN + t0 + tok)) * 8 + hh) * E;
        *(float4*)&sq[tok * STR + e4] = *(const float4*)&q[e4];
    }
    __syncthreads();

    int w = tid >> 5, lane = tid & 31;
    int r0 = w * 8;

    for (int nhp = 0; nhp < NHASH; nhp += 2) {
        float acc0[8], acc1[8];
        #pragma unroll
        for (int r = 0; r < 8; r++) { acc0[r] = 0.f; acc1[r] = 0.f; }
        const float* rrow0 = &srot[((nhp    ) * 32 + lane) * STR];
        const float* rrow1 = &srot[((nhp + 1) * 32 + lane) * STR];
        #pragma unroll 4
        for (int e4 = 0; e4 < 64; e4 += 4) {
            float4 rv0 = *(const float4*)&rrow0[e4];
            float4 rv1 = *(const float4*)&rrow1[e4];
            #pragma unroll
            for (int r = 0; r < 8; r++) {
                float4 qv = *(const float4*)&sq[(r0 + r) * STR + e4];
                acc0[r] = fmaf(qv.x, rv0.x, fmaf(qv.y, rv0.y, fmaf(qv.z, rv0.z, fmaf(qv.w, rv0.w, acc0[r]))));
                acc1[r] = fmaf(qv.x, rv1.x, fmaf(qv.y, rv1.y, fmaf(qv.z, rv1.z, fmaf(qv.w, rv1.w, acc1[r]))));
            }
        }
        #pragma unroll
        for (int half = 0; half < 2; half++) {
            int nh = nhp + half;
            #pragma unroll
            for (int r = 0; r < 8; r++) {
                float a = half ? acc1[r] : acc0[r];
                float bestv; int besti;
                if (-a > a) { bestv = -a; besti = lane + 32; }
                else        { bestv =  a; besti = lane; }
                #pragma unroll
                for (int off = 16; off; off >>= 1) {
                    float ov = __shfl_down_sync(0xffffffffu, bestv, off);
                    int   oi = __shfl_down_sync(0xffffffffu, besti, off);
                    if (ov > bestv || (ov == bestv && oi < besti)) { bestv = ov; besti = oi; }
                }
                besti = __shfl_sync(0xffffffffu, besti, 0);
                if (lane == 0) {
                    int t = t0 + r0 + r;
                    g_buckets[(B * NHASH + nh) * TLEN + t] = (unsigned char)besti;
                    atomicAdd(&g_counts[B * NGBUCK + nh * NBUCK + besti], 1);
                }
            }
        }
    }
}

__global__ void scan_kernel(int Boff) {
    __shared__ int s[NGBUCK];
    int B = blockIdx.x + Boff, tid = threadIdx.x;
    s[tid] = g_counts[B * NGBUCK + tid];
    __syncthreads();
    for (int off = 1; off < NGBUCK; off <<= 1) {
        int v = (tid >= off) ? s[tid - off] : 0;
        __syncthreads();
        s[tid] += v;
        __syncthreads();
    }
    g_offsets[B * NGBUCK + tid] = tid ? s[tid - 1] : 0;
}

// Stable counting-sort scatter: 256 threads, 16 passes (R10 known-good).
__global__ void scatter_kernel(int Boff) {
    int B = (blockIdx.x >> 3) + Boff, nh = blockIdx.x & 7;
    __shared__ int cnt[NBUCK];
    __shared__ int wcnt[8][NBUCK];
    int tid = threadIdx.x, w = tid >> 5, lane = tid & 31;

    if (tid < NBUCK) cnt[tid] = g_offsets[B * NGBUCK + nh * NBUCK + tid];
    const unsigned char* src = &g_buckets[(B * NHASH + nh) * TLEN];
    int* dst = &g_st[B * (NHASH * TLEN)];

    for (int pass = 0; pass < 16; pass++) {
        wcnt[w][lane] = 0; wcnt[w][lane + 32] = 0;
        __syncthreads();
        int t = pass * 256 + tid;
        int bk = src[t];
        unsigned mask = __match_any_sync(0xffffffffu, bk);
        int rank = __popc(mask & ((1u << lane) - 1u));
        if (rank == 0) wcnt[w][bk] = __popc(mask);
        __syncthreads();
        int pos = cnt[bk] + rank;
        #pragma unroll
        for (int w2 = 0; w2 < 8; w2++)
            if (w2 < w) pos += wcnt[w2][bk];
        dst[pos] = t;
        __syncthreads();
        if (tid < NBUCK) {
            int s = 0;
            #pragma unroll
            for (int w2 = 0; w2 < 8; w2++) s += wcnt[w2][tid];
            cnt[tid] += s;
        }
        __syncthreads();
    }
}

// ---------------- helpers ----------------
__device__ __forceinline__ u32 swz(int row, int chunk) {
    return (u32)(row * 128 + (((chunk ^ (row & 7)) & 7) << 4));
}
__device__ __forceinline__ void ldsm_x4(u32* r, u32 addr) {
    asm volatile("ldmatrix.sync.aligned.m8n8.x4.shared.b16 {%0,%1,%2,%3}, [%4];"
                 : "=r"(r[0]), "=r"(r[1]), "=r"(r[2]), "=r"(r[3]) : "r"(addr));
}
__device__ __forceinline__ void ldsm_x4t(u32* r, u32 addr) {
    asm volatile("ldmatrix.sync.aligned.m8n8.x4.trans.shared.b16 {%0,%1,%2,%3}, [%4];"
                 : "=r"(r[0]), "=r"(r[1]), "=r"(r[2]), "=r"(r[3]) : "r"(addr));
}
__device__ __forceinline__ void mma_bf16(float* d, const u32* a, u32 b0, u32 b1) {
    asm volatile("mma.sync.aligned.m16n8k16.row.col.f32.bf16.bf16.f32 "
                 "{%0,%1,%2,%3},{%4,%5,%6,%7},{%8,%9},{%0,%1,%2,%3};"
                 : "+f"(d[0]), "+f"(d[1]), "+f"(d[2]), "+f"(d[3])
                 : "r"(a[0]), "r"(a[1]), "r"(a[2]), "r"(a[3]), "r"(b0), "r"(b1));
}
__device__ __forceinline__ u32 prmt7632(u32 a, u32 b) {
    u32 r;
    asm("prmt.b32 %0, %1, %2, 0x7632;" : "=r"(r) : "r"(a), "r"(b));
    return r;
}
// Veltkamp truncation split: hi = trunc-bf16(x) (exact residual), lo = bf16(x-hi)
__device__ __forceinline__ void split2(float a, float b, u32& hi, u32& lo) {
    u32 ua = __float_as_uint(a) & 0xFFFF0000u;
    u32 ub = __float_as_uint(b) & 0xFFFF0000u;
    hi = prmt7632(ua, ub);
    float la = a - __uint_as_float(ua);
    float lb = b - __uint_as_float(ub);
    lo = prmt7632(__float_as_uint(la), __float_as_uint(lb));
}
__device__ __forceinline__ void split8v(const float* x, uint4& hi, uint4& lo) {
    u32 h[4], l[4];
    #pragma unroll
    for (int p = 0; p < 4; p++) split2(x[2*p], x[2*p+1], h[p], l[p]);
    hi = make_uint4(h[0], h[1], h[2], h[3]);
    lo = make_uint4(l[0], l[1], l[2], l[3]);
}

// ---------------- tensor-core attention (R10 exact) ----------------
#define SM_KLO 16384
#define SM_VHI 32768
#define SM_VLO 49152
#define SM_PO  65536
#define SM_INV 82944
#define SM_RDS 83456
#define SM_STK 83968
#define ATTN_SMEM 84480
#define POSTR 68

__global__ void __launch_bounds__(256, 2) attn_kernel(const float* __restrict__ qk,
                                                      const float* __restrict__ vv,
                                                      int Boff) {
    extern __shared__ char smem[];
    float* po   = (float*)(smem + SM_PO);
    float* invn = (float*)(smem + SM_INV);
    float* reds = (float*)(smem + SM_RDS);
    int*   stk  = (int*)  (smem + SM_STK);

    int tid = threadIdx.x;
    int Bq = (blockIdx.x >> 9) + Boff;
    int c  = blockIdx.x & (CHUNKS - 1);
    int cp = (c + CHUNKS - 1) & (CHUNKS - 1);
    int b = Bq >> 3, hh = Bq & 7;
    int nh = c >> 6;

    if (tid < 128) {
        int p = (tid < 64) ? (c * CS + tid) : (cp * CS + tid - 64);
        stk[tid] = g_st[Bq * (NHASH * TLEN) + p];
    }
    __syncthreads();

    // ---- gather (L2-resident inputs) + truncation split + key norms ----
    {
        int seg = tid & 7;              // 8-col segment of a row
        #pragma unroll
        for (int pass = 0; pass < 4; pass++) {
            int j = (tid >> 3) + pass * 32;
            size_t base = (((size_t)(b * TLEN + stk[j])) * 8 + hh) * E + seg * 8;
            float x[8], y[8];
            *(float4*)&x[0] = *(const float4*)&qk[base];
            *(float4*)&x[4] = *(const float4*)&qk[base + 4];
            *(float4*)&y[0] = *(const float4*)&vv[base];
            *(float4*)&y[4] = *(const float4*)&vv[base + 4];
            u32 off = swz(j, seg);

            uint4 hi, lo;
            split8v(x, hi, lo);
            *(uint4*)(smem + off)          = hi;
            *(uint4*)(smem + SM_KLO + off) = lo;
            split8v(y, hi, lo);
            *(uint4*)(smem + SM_VHI + off) = hi;
            *(uint4*)(smem + SM_VLO + off) = lo;

            float ss = 0.f;
            #pragma unroll
            for (int i = 0; i < 8; i++) ss = fmaf(x[i], x[i], ss);
            ss += __shfl_xor_sync(0xffffffffu, ss, 1);
            ss += __shfl_xor_sync(0xffffffffu, ss, 2);
            ss += __shfl_xor_sync(0xffffffffu, ss, 4);
            if (seg == 0) invn[j] = 1.f / fmaxf(sqrtf(ss), 1e-12f);
        }
    }
    __syncthreads();

    int w = tid >> 5, lane = tid & 31;
    int wm = w & 3, wn = w >> 2;
    int m0 = wm * 16, n0 = wn * 64;
    int g  = lane >> 3, lr = lane & 7;
    u32 kb = (u32)__cvta_generic_to_shared(smem);

    // ---- QK: D[64q,128k] via 3 split MMAs ----
    float acc[8][4];
    #pragma unroll
    for (int nt = 0; nt < 8; nt++) { acc[nt][0]=0.f; acc[nt][1]=0.f; acc[nt][2]=0.f; acc[nt][3]=0.f; }

    #pragma unroll
    for (int ck = 0; ck < 4; ck++) {
        int arow = m0 + ((g & 1) << 3) + lr;
        u32 aoff = swz(arow, 2 * ck + (g >> 1));
        u32 aH[4], aL[4];
        ldsm_x4(aH, kb + aoff);
        ldsm_x4(aL, kb + SM_KLO + aoff);
        #pragma unroll
        for (int p = 0; p < 4; p++) {
            int brow = n0 + 16 * p + ((g >> 1) << 3) + lr;
            u32 boff = swz(brow, 2 * ck + (g & 1));
            u32 bH[4], bL[4];
            ldsm_x4(bH, kb + boff);
            ldsm_x4(bL, kb + SM_KLO + boff);
            mma_bf16(acc[2*p],   aH, bH[0], bH[1]);
            mma_bf16(acc[2*p+1], aH, bH[2], bH[3]);
            mma_bf16(acc[2*p],   aH, bL[0], bL[1]);
            mma_bf16(acc[2*p+1], aH, bL[2], bL[3]);
            mma_bf16(acc[2*p],   aL, bH[0], bH[1]);
            mma_bf16(acc[2*p+1], aL, bH[2], bH[3]);
        }
    }

    // ---- scale by key inv-norm, self-mask, bound-max softmax ----
    int rA = m0 + (lane >> 2), rB = rA + 8;
    int tiA = stk[rA], tiB = stk[rB];
    float mA = 1.0f / invn[rA];
    float mB = 1.0f / invn[rB];

    float sA = 0.f, sB = 0.f;
    #pragma unroll
    for (int nt = 0; nt < 8; nt++) {
        int c0 = n0 + 8 * nt + 2 * (lane & 3);
        float i0 = invn[c0], i1 = invn[c0 + 1];
        int tc0 = stk[c0], tc1 = stk[c0 + 1];
        float d0 = acc[nt][0] * i0, d1 = acc[nt][1] * i1;
        float d2 = acc[nt][2] * i0, d3 = acc[nt][3] * i1;
        if (tc0 == tiA) d0 = -50000.f;
        if (tc1 == tiA) d1 = -50000.f;
        if (tc0 == tiB) d2 = -50000.f;
        if (tc1 == tiB) d3 = -50000.f;
        acc[nt][0] = __expf(d0 - mA);
        acc[nt][1] = __expf(d1 - mA);
        acc[nt][2] = __expf(d2 - mB);
        acc[nt][3] = __expf(d3 - mB);
        sA += acc[nt][0] + acc[nt][1];
        sB += acc[nt][2] + acc[nt][3];
    }
    sA += __shfl_xor_sync(0xffffffffu, sA, 1);
    sA += __shfl_xor_sync(0xffffffffu, sA, 2);
    sB += __shfl_xor_sync(0xffffffffu, sB, 1);
    sB += __shfl_xor_sync(0xffffffffu, sB, 2);

    int ridx = (wm * 2 + wn) * 16 + (lane >> 2);
    int pidx = (wm * 2 + (1 - wn)) * 16 + (lane >> 2);
    if ((lane & 3) == 0) { reds[ridx] = sA; reds[ridx + 8] = sB; }
    __syncthreads();
    sA += reds[pidx]; sB += reds[pidx + 8];
    float invsA = 1.f / sA, invsB = 1.f / sB;
    float lseA = mA + __logf(sA), lseB = mB + __logf(sB);

    // ---- P -> bf16 hi/lo fragments via truncation split ----
    u32 phA[8], phB[8], plA[8], plB[8];
    #pragma unroll
    for (int nt = 0; nt < 8; nt++) {
        split2(acc[nt][0], acc[nt][1], phA[nt], plA[nt]);
        split2(acc[nt][2], acc[nt][3], phB[nt], plB[nt]);
    }

    // ---- PV: out[64q,64d] partials over this warp's 64 j's ----
    float av[8][4];
    #pragma unroll
    for (int nt = 0; nt < 8; nt++) { av[nt][0]=0.f; av[nt][1]=0.f; av[nt][2]=0.f; av[nt][3]=0.f; }

    #pragma unroll
    for (int k = 0; k < 4; k++) {
        u32 aH[4] = { phA[2*k], phB[2*k], phA[2*k+1], phB[2*k+1] };
        u32 aL[4] = { plA[2*k], plB[2*k], plA[2*k+1], plB[2*k+1] };
        int vrow = n0 + 16 * k + ((g & 1) << 3) + lr;
        #pragma unroll
        for (int p = 0; p < 4; p++) {
            u32 voff = swz(vrow, 2 * p + (g >> 1));
            u32 bH[4], bL[4];
            ldsm_x4t(bH, kb + SM_VHI + voff);
            ldsm_x4t(bL, kb + SM_VLO + voff);
            mma_bf16(av[2*p],   aH, bH[0], bH[1]);
            mma_bf16(av[2*p+1], aH, bH[2], bH[3]);
            mma_bf16(av[2*p],   aH, bL[0], bL[1]);
            mma_bf16(av[2*p+1], aH, bL[2], bL[3]);
            mma_bf16(av[2*p],   aL, bH[0], bH[1]);
            mma_bf16(av[2*p+1], aL, bH[2], bH[3]);
        }
    }

    // ---- combine warp-pair partials; direct fp16 store ----
    if (wn == 1) {
        #pragma unroll
        for (int nt = 0; nt < 8; nt++) {
            int c0 = 8 * nt + 2 * (lane & 3);
            po[rA * POSTR + c0]     = av[nt][0];
            po[rA * POSTR + c0 + 1] = av[nt][1];
            po[rB * POSTR + c0]     = av[nt][2];
            po[rB * POSTR + c0 + 1] = av[nt][3];
        }
    }
    __syncthreads();
    if (wn == 0) {
        size_t orowA = ((size_t)((Bq * NHASH + nh) * TLEN + tiA)) * E;
        size_t orowB = ((size_t)((Bq * NHASH + nh) * TLEN + tiB)) * E;
        #pragma unroll
        for (int nt = 0; nt < 8; nt++) {
            int c0 = 8 * nt + 2 * (lane & 3);
            float o0 = (av[nt][0] + po[rA * POSTR + c0])     * invsA;
            float o1 = (av[nt][1] + po[rA * POSTR + c0 + 1]) * invsA;
            float o2 = (av[nt][2] + po[rB * POSTR + c0])     * invsB;
            float o3 = (av[nt][3] + po[rB * POSTR + c0 + 1]) * invsB;
            __half2 hA = __floats2half2_rn(o0, o1);
            __half2 hB = __floats2half2_rn(o2, o3);
            *(u32*)&g_o[orowA + c0] = *(u32*)&hA;
            *(u32*)&g_o[orowB + c0] = *(u32*)&hB;
        }
        if ((lane & 3) == 0) {
            g_logits[(Bq * NHASH + nh) * TLEN + tiA] = lseA;
            g_logits[(Bq * NHASH + nh) * TLEN + tiB] = lseB;
        }
    }
}

// ---------------- combine (R10 exact) ----------------
__global__ void combine_kernel(float* __restrict__ out) {
    int gid = blockIdx.x * blockDim.x + threadIdx.x;
    int d4 = (gid & 15) << 2;
    int token = gid >> 4;
    int B = token >> 12, t = token & (TLEN - 1);

    float l[NHASH];
    float mx = -INFINITY;
    #pragma unroll
    for (int nh = 0; nh < NHASH; nh++) {
        l[nh] = g_logits[(B * NHASH + nh) * TLEN + t];
        mx = fmaxf(mx, l[nh]);
    }
    float s = 0.f;
    #pragma unroll
    for (int nh = 0; nh < NHASH; nh++) { l[nh] = __expf(l[nh] - mx); s += l[nh]; }
    float inv = 1.f / s;
    float4 acc = make_float4(0.f, 0.f, 0.f, 0.f);
    #pragma unroll
    for (int nh = 0; nh < NHASH; nh++) {
        float wgt = l[nh] * inv;
        uint2 raw = *(const uint2*)&g_o[((size_t)((B * NHASH + nh) * TLEN + t)) * E + d4];
        float2 f01 = __half22float2(*(__half2*)&raw.x);
        float2 f23 = __half22float2(*(__half2*)&raw.y);
        acc.x = fmaf(wgt, f01.x, acc.x);
        acc.y = fmaf(wgt, f01.y, acc.y);
        acc.z = fmaf(wgt, f23.x, acc.z);
        acc.w = fmaf(wgt, f23.y, acc.w);
    }
    *(float4*)&out[((size_t)token) * E + d4] = acc;
}

extern "C" void kernel_launch(void* const* d_in, const int* in_sizes, int n_in,
                              void* d_out, int out_size) {
    const float* qk  = (const float*)d_in[0];
    // d_in[1] = k is unused by the reference (shared-QK attention)
    const float* v   = (const float*)d_in[2];
    const float* rot = (const float*)d_in[3];
    float* out = (float*)d_out;

    const int hash_smem = (256 * STR + 64 * STR) * (int)sizeof(float);
    cudaFuncSetAttribute(attn_kernel, cudaFuncAttributeMaxDynamicSharedMemorySize, ATTN_SMEM);
    cudaFuncSetAttribute(hash_kernel, cudaFuncAttributeMaxDynamicSharedMemorySize, hash_smem);

    cudaStream_t s2 = 0;
    cudaEvent_t eF = 0, eJ = 0;
    bool forked = false;
    {
        cudaStream_t tmp;
        if (cudaStreamCreateWithFlags(&tmp, cudaStreamNonBlocking) == cudaSuccess) {
            if (cudaEventCreateWithFlags(&eF, cudaEventDisableTiming) == cudaSuccess &&
                cudaEventCreateWithFlags(&eJ, cudaEventDisableTiming) == cudaSuccess) {
                s2 = tmp;
                forked = true;
            }
        }
    }
    cudaStream_t sB = forked ? s2 : (cudaStream_t)0;

    zero_counts_kernel<<<32, 256, 0, 0>>>(0);   // zeros ALL NB*NGBUCK counters (grid 32 x 256)
    if (forked) {
        cudaEventRecord(eF, 0);
        cudaStreamWaitEvent(s2, eF, 0);
    }

    hash_kernel   <<<(NB / 2) * 64,     256, hash_smem, 0 >>>(qk, rot, 0);
    hash_kernel   <<<(NB / 2) * 64,     256, hash_smem, sB>>>(qk, rot, NB / 2);
    scan_kernel   <<<NB / 2,            NGBUCK, 0,      0 >>>(0);
    scatter_kernel<<<(NB / 2) * NHASH,  256, 0,         0 >>>(0);
    attn_kernel   <<<(NB / 2) * CHUNKS, 256, ATTN_SMEM, 0 >>>(qk, v, 0);
    scan_kernel   <<<NB / 2,            NGBUCK, 0,      sB>>>(NB / 2);
    scatter_kernel<<<(NB / 2) * NHASH,  256, 0,         sB>>>(NB / 2);
    attn_kernel   <<<(NB / 2) * CHUNKS, 256, ATTN_SMEM, sB>>>(qk, v, NB / 2);

    if (forked) {
        cudaEventRecord(eJ, s2);
        cudaStreamWaitEvent(0, eJ, 0);
    }
    combine_kernel<<<NB * TLEN * E / 4 / 256, 256>>>(out);
}

// round 15
// speedup vs baseline: 1.4966x; 1.0057x over previous
#include <cuda_runtime.h>
#include <cuda_bf16.h>
#include <cuda_fp16.h>
#include <stdint.h>
#include <cstdint>
#include <math.h>

// Problem constants
#define NB 16        // B = b*h
#define TLEN 4096    // sequence length
#define NHASH 8
#define NBUCK 64     // local buckets per round
#define NGBUCK 512   // global buckets per B-row
#define CHUNKS 512   // chunks per B-row
#define CS 64        // chunk size
#define E 64         // head dim
#define STR 68       // smem row stride (floats) for hash kernel

typedef unsigned int u32;

// Scratch (device globals — no allocations allowed)
__device__ unsigned char g_buckets[NB * NHASH * TLEN];
__device__ int    g_counts [NB * NGBUCK];
__device__ int    g_offsets[NB * NGBUCK];
__device__ int    g_st     [NB * NHASH * TLEN];
__device__ float  g_logits [NB * NHASH * TLEN];
__device__ __half g_o      [(size_t)NB * NHASH * TLEN * E];   // 64MB (fp16 per-round outputs)

__global__ void zero_counts_kernel(int Boff) {
    int i = blockIdx.x * blockDim.x + threadIdx.x;
    g_counts[Boff * NGBUCK + i] = 0;
}

// ---------------- hash: 4 hash rounds x 8 tokens per accumulator pass ----------------
__global__ void __launch_bounds__(256, 2) hash_kernel(const float* __restrict__ qk,
                                                      const float* __restrict__ rot,
                                                      int Boff) {
    extern __shared__ float hsm[];
    float* srot = hsm;               // 256 rows x STR
    float* sq   = srot + 256 * STR;  // 64 tokens x STR

    int tid = threadIdx.x;
    int B  = (blockIdx.x >> 6) + Boff;
    int t0 = (blockIdx.x & 63) << 6;
    int b = B >> 3, hh = B & 7;

    for (int idx = tid; idx < 64 * NHASH * 32; idx += 256) {
        int e = idx >> 8, r = idx & 255;
        srot[r * STR + e] = rot[idx];
    }
    for (int idx = tid; idx < 64 * 16; idx += 256) {
        int tok = idx >> 4, e4 = (idx & 15) << 2;
        const float* q = qk + (((size_t)(b * TLEN + t0 + tok)) * 8 + hh) * E;
        *(float4*)&sq[tok * STR + e4] = *(const float4*)&q[e4];
    }
    __syncthreads();

    int w = tid >> 5, lane = tid & 31;
    int r0 = w * 8;

    #pragma unroll
    for (int nhp = 0; nhp < NHASH; nhp += 4) {
        float acc[4][8];
        #pragma unroll
        for (int hq = 0; hq < 4; hq++)
            #pragma unroll
            for (int r = 0; r < 8; r++) acc[hq][r] = 0.f;

        #pragma unroll 4
        for (int e4 = 0; e4 < 64; e4 += 4) {
            float4 rv0 = *(const float4*)&srot[((nhp + 0) * 32 + lane) * STR + e4];
            float4 rv1 = *(const float4*)&srot[((nhp + 1) * 32 + lane) * STR + e4];
            float4 rv2 = *(const float4*)&srot[((nhp + 2) * 32 + lane) * STR + e4];
            float4 rv3 = *(const float4*)&srot[((nhp + 3) * 32 + lane) * STR + e4];
            #pragma unroll
            for (int r = 0; r < 8; r++) {
                float4 qv = *(const float4*)&sq[(r0 + r) * STR + e4];
                acc[0][r] = fmaf(qv.x, rv0.x, fmaf(qv.y, rv0.y, fmaf(qv.z, rv0.z, fmaf(qv.w, rv0.w, acc[0][r]))));
                acc[1][r] = fmaf(qv.x, rv1.x, fmaf(qv.y, rv1.y, fmaf(qv.z, rv1.z, fmaf(qv.w, rv1.w, acc[1][r]))));
                acc[2][r] = fmaf(qv.x, rv2.x, fmaf(qv.y, rv2.y, fmaf(qv.z, rv2.z, fmaf(qv.w, rv2.w, acc[2][r]))));
                acc[3][r] = fmaf(qv.x, rv3.x, fmaf(qv.y, rv3.y, fmaf(qv.z, rv3.z, fmaf(qv.w, rv3.w, acc[3][r]))));
            }
        }

        #pragma unroll
        for (int hq = 0; hq < 4; hq++) {
            int nh = nhp + hq;
            #pragma unroll
            for (int r = 0; r < 8; r++) {
                float a = acc[hq][r];
                float bestv; int besti;
                if (-a > a) { bestv = -a; besti = lane + 32; }
                else        { bestv =  a; besti = lane; }
                #pragma unroll
                for (int off = 16; off; off >>= 1) {
                    float ov = __shfl_down_sync(0xffffffffu, bestv, off);
                    int   oi = __shfl_down_sync(0xffffffffu, besti, off);
                    if (ov > bestv || (ov == bestv && oi < besti)) { bestv = ov; besti = oi; }
                }
                besti = __shfl_sync(0xffffffffu, besti, 0);
                if (lane == 0) {
                    int t = t0 + r0 + r;
                    g_buckets[(B * NHASH + nh) * TLEN + t] = (unsigned char)besti;
                    atomicAdd(&g_counts[B * NGBUCK + nh * NBUCK + besti], 1);
                }
            }
        }
    }
}

__global__ void scan_kernel(int Boff) {
    __shared__ int s[NGBUCK];
    int B = blockIdx.x + Boff, tid = threadIdx.x;
    s[tid] = g_counts[B * NGBUCK + tid];
    __syncthreads();
    for (int off = 1; off < NGBUCK; off <<= 1) {
        int v = (tid >= off) ? s[tid - off] : 0;
        __syncthreads();
        s[tid] += v;
        __syncthreads();
    }
    g_offsets[B * NGBUCK + tid] = tid ? s[tid - 1] : 0;
}

// Stable counting-sort scatter: 256 threads, 16 passes (R10 known-good).
__global__ void scatter_kernel(int Boff) {
    int B = (blockIdx.x >> 3) + Boff, nh = blockIdx.x & 7;
    __shared__ int cnt[NBUCK];
    __shared__ int wcnt[8][NBUCK];
    int tid = threadIdx.x, w = tid >> 5, lane = tid & 31;

    if (tid < NBUCK) cnt[tid] = g_offsets[B * NGBUCK + nh * NBUCK + tid];
    const unsigned char* src = &g_buckets[(B * NHASH + nh) * TLEN];
    int* dst = &g_st[B * (NHASH * TLEN)];

    for (int pass = 0; pass < 16; pass++) {
        wcnt[w][lane] = 0; wcnt[w][lane + 32] = 0;
        __syncthreads();
        int t = pass * 256 + tid;
        int bk = src[t];
        unsigned mask = __match_any_sync(0xffffffffu, bk);
        int rank = __popc(mask & ((1u << lane) - 1u));
        if (rank == 0) wcnt[w][bk] = __popc(mask);
        __syncthreads();
        int pos = cnt[bk] + rank;
        #pragma unroll
        for (int w2 = 0; w2 < 8; w2++)
            if (w2 < w) pos += wcnt[w2][bk];
        dst[pos] = t;
        __syncthreads();
        if (tid < NBUCK) {
            int s = 0;
            #pragma unroll
            for (int w2 = 0; w2 < 8; w2++) s += wcnt[w2][tid];
            cnt[tid] += s;
        }
        __syncthreads();
    }
}

// ---------------- helpers ----------------
__device__ __forceinline__ u32 swz(int row, int chunk) {
    return (u32)(row * 128 + (((chunk ^ (row & 7)) & 7) << 4));
}
__device__ __forceinline__ void ldsm_x4(u32* r, u32 addr) {
    asm volatile("ldmatrix.sync.aligned.m8n8.x4.shared.b16 {%0,%1,%2,%3}, [%4];"
                 : "=r"(r[0]), "=r"(r[1]), "=r"(r[2]), "=r"(r[3]) : "r"(addr));
}
__device__ __forceinline__ void ldsm_x4t(u32* r, u32 addr) {
    asm volatile("ldmatrix.sync.aligned.m8n8.x4.trans.shared.b16 {%0,%1,%2,%3}, [%4];"
                 : "=r"(r[0]), "=r"(r[1]), "=r"(r[2]), "=r"(r[3]) : "r"(addr));
}
__device__ __forceinline__ void mma_bf16(float* d, const u32* a, u32 b0, u32 b1) {
    asm volatile("mma.sync.aligned.m16n8k16.row.col.f32.bf16.bf16.f32 "
                 "{%0,%1,%2,%3},{%4,%5,%6,%7},{%8,%9},{%0,%1,%2,%3};"
                 : "+f"(d[0]), "+f"(d[1]), "+f"(d[2]), "+f"(d[3])
                 : "r"(a[0]), "r"(a[1]), "r"(a[2]), "r"(a[3]), "r"(b0), "r"(b1));
}
__device__ __forceinline__ u32 prmt7632(u32 a, u32 b) {
    u32 r;
    asm("prmt.b32 %0, %1, %2, 0x7632;" : "=r"(r) : "r"(a), "r"(b));
    return r;
}
// Veltkamp truncation split: hi = trunc-bf16(x) (exact residual), lo = bf16(x-hi)
__device__ __forceinline__ void split2(float a, float b, u32& hi, u32& lo) {
    u32 ua = __float_as_uint(a) & 0xFFFF0000u;
    u32 ub = __float_as_uint(b) & 0xFFFF0000u;
    hi = prmt7632(ua, ub);
    float la = a - __uint_as_float(ua);
    float lb = b - __uint_as_float(ub);
    lo = prmt7632(__float_as_uint(la), __float_as_uint(lb));
}
__device__ __forceinline__ void split8v(const float* x, uint4& hi, uint4& lo) {
    u32 h[4], l[4];
    #pragma unroll
    for (int p = 0; p < 4; p++) split2(x[2*p], x[2*p+1], h[p], l[p]);
    hi = make_uint4(h[0], h[1], h[2], h[3]);
    lo = make_uint4(l[0], l[1], l[2], l[3]);
}

// ---------------- tensor-core attention (R10/R14 exact) ----------------
#define SM_KLO 16384
#define SM_VHI 32768
#define SM_VLO 49152
#define SM_PO  65536
#define SM_INV 82944
#define SM_RDS 83456
#define SM_STK 83968
#define ATTN_SMEM 84480
#define POSTR 68

__global__ void __launch_bounds__(256, 2) attn_kernel(const float* __restrict__ qk,
                                                      const float* __restrict__ vv,
                                                      int Boff) {
    extern __shared__ char smem[];
    float* po   = (float*)(smem + SM_PO);
    float* invn = (float*)(smem + SM_INV);
    float* reds = (float*)(smem + SM_RDS);
    int*   stk  = (int*)  (smem + SM_STK);

    int tid = threadIdx.x;
    int Bq = (blockIdx.x >> 9) + Boff;
    int c  = blockIdx.x & (CHUNKS - 1);
    int cp = (c + CHUNKS - 1) & (CHUNKS - 1);
    int b = Bq >> 3, hh = Bq & 7;
    int nh = c >> 6;

    if (tid < 128) {
        int p = (tid < 64) ? (c * CS + tid) : (cp * CS + tid - 64);
        stk[tid] = g_st[Bq * (NHASH * TLEN) + p];
    }
    __syncthreads();

    // ---- gather (L2-resident inputs) + truncation split + key norms ----
    {
        int seg = tid & 7;              // 8-col segment of a row
        #pragma unroll
        for (int pass = 0; pass < 4; pass++) {
            int j = (tid >> 3) + pass * 32;
            size_t base = (((size_t)(b * TLEN + stk[j])) * 8 + hh) * E + seg * 8;
            float x[8], y[8];
            *(float4*)&x[0] = *(const float4*)&qk[base];
            *(float4*)&x[4] = *(const float4*)&qk[base + 4];
            *(float4*)&y[0] = *(const float4*)&vv[base];
            *(float4*)&y[4] = *(const float4*)&vv[base + 4];
            u32 off = swz(j, seg);

            uint4 hi, lo;
            split8v(x, hi, lo);
            *(uint4*)(smem + off)          = hi;
            *(uint4*)(smem + SM_KLO + off) = lo;
            split8v(y, hi, lo);
            *(uint4*)(smem + SM_VHI + off) = hi;
            *(uint4*)(smem + SM_VLO + off) = lo;

            float ss = 0.f;
            #pragma unroll
            for (int i = 0; i < 8; i++) ss = fmaf(x[i], x[i], ss);
            ss += __shfl_xor_sync(0xffffffffu, ss, 1);
            ss += __shfl_xor_sync(0xffffffffu, ss, 2);
            ss += __shfl_xor_sync(0xffffffffu, ss, 4);
            if (seg == 0) invn[j] = 1.f / fmaxf(sqrtf(ss), 1e-12f);
        }
    }
    __syncthreads();

    int w = tid >> 5, lane = tid & 31;
    int wm = w & 3, wn = w >> 2;
    int m0 = wm * 16, n0 = wn * 64;
    int g  = lane >> 3, lr = lane & 7;
    u32 kb = (u32)__cvta_generic_to_shared(smem);

    // ---- QK: D[64q,128k] via 3 split MMAs ----
    float acc[8][4];
    #pragma unroll
    for (int nt = 0; nt < 8; nt++) { acc[nt][0]=0.f; acc[nt][1]=0.f; acc[nt][2]=0.f; acc[nt][3]=0.f; }

    #pragma unroll
    for (int ck = 0; ck < 4; ck++) {
        int arow = m0 + ((g & 1) << 3) + lr;
        u32 aoff = swz(arow, 2 * ck + (g >> 1));
        u32 aH[4], aL[4];
        ldsm_x4(aH, kb + aoff);
        ldsm_x4(aL, kb + SM_KLO + aoff);
        #pragma unroll
        for (int p = 0; p < 4; p++) {
            int brow = n0 + 16 * p + ((g >> 1) << 3) + lr;
            u32 boff = swz(brow, 2 * ck + (g & 1));
            u32 bH[4], bL[4];
            ldsm_x4(bH, kb + boff);
            ldsm_x4(bL, kb + SM_KLO + boff);
            mma_bf16(acc[2*p],   aH, bH[0], bH[1]);
            mma_bf16(acc[2*p+1], aH, bH[2], bH[3]);
            mma_bf16(acc[2*p],   aH, bL[0], bL[1]);
            mma_bf16(acc[2*p+1], aH, bL[2], bL[3]);
            mma_bf16(acc[2*p],   aL, bH[0], bH[1]);
            mma_bf16(acc[2*p+1], aL, bH[2], bH[3]);
        }
    }

    // ---- scale by key inv-norm, self-mask, bound-max softmax ----
    int rA = m0 + (lane >> 2), rB = rA + 8;
    int tiA = stk[rA], tiB = stk[rB];
    float mA = 1.0f / invn[rA];
    float mB = 1.0f / invn[rB];

    float sA = 0.f, sB = 0.f;
    #pragma unroll
    for (int nt = 0; nt < 8; nt++) {
        int c0 = n0 + 8 * nt + 2 * (lane & 3);
        float i0 = invn[c0], i1 = invn[c0 + 1];
        int tc0 = stk[c0], tc1 = stk[c0 + 1];
        float d0 = acc[nt][0] * i0, d1 = acc[nt][1] * i1;
        float d2 = acc[nt][2] * i0, d3 = acc[nt][3] * i1;
        if (tc0 == tiA) d0 = -50000.f;
        if (tc1 == tiA) d1 = -50000.f;
        if (tc0 == tiB) d2 = -50000.f;
        if (tc1 == tiB) d3 = -50000.f;
        acc[nt][0] = __expf(d0 - mA);
        acc[nt][1] = __expf(d1 - mA);
        acc[nt][2] = __expf(d2 - mB);
        acc[nt][3] = __expf(d3 - mB);
        sA += acc[nt][0] + acc[nt][1];
        sB += acc[nt][2] + acc[nt][3];
    }
    sA += __shfl_xor_sync(0xffffffffu, sA, 1);
    sA += __shfl_xor_sync(0xffffffffu, sA, 2);
    sB += __shfl_xor_sync(0xffffffffu, sB, 1);
    sB += __shfl_xor_sync(0xffffffffu, sB, 2);

    int ridx = (wm * 2 + wn) * 16 + (lane >> 2);
    int pidx = (wm * 2 + (1 - wn)) * 16 + (lane >> 2);
    if ((lane & 3) == 0) { reds[ridx] = sA; reds[ridx + 8] = sB; }
    __syncthreads();
    sA += reds[pidx]; sB += reds[pidx + 8];
    float invsA = 1.f / sA, invsB = 1.f / sB;
    float lseA = mA + __logf(sA), lseB = mB + __logf(sB);

    // ---- P -> bf16 hi/lo fragments via truncation split ----
    u32 phA[8], phB[8], plA[8], plB[8];
    #pragma unroll
    for (int nt = 0; nt < 8; nt++) {
        split2(acc[nt][0], acc[nt][1], phA[nt], plA[nt]);
        split2(acc[nt][2], acc[nt][3], phB[nt], plB[nt]);
    }

    // ---- PV: out[64q,64d] partials over this warp's 64 j's ----
    float av[8][4];
    #pragma unroll
    for (int nt = 0; nt < 8; nt++) { av[nt][0]=0.f; av[nt][1]=0.f; av[nt][2]=0.f; av[nt][3]=0.f; }

    #pragma unroll
    for (int k = 0; k < 4; k++) {
        u32 aH[4] = { phA[2*k], phB[2*k], phA[2*k+1], phB[2*k+1] };
        u32 aL[4] = { plA[2*k], plB[2*k], plA[2*k+1], plB[2*k+1] };
        int vrow = n0 + 16 * k + ((g & 1) << 3) + lr;
        #pragma unroll
        for (int p = 0; p < 4; p++) {
            u32 voff = swz(vrow, 2 * p + (g >> 1));
            u32 bH[4], bL[4];
            ldsm_x4t(bH, kb + SM_VHI + voff);
            ldsm_x4t(bL, kb + SM_VLO + voff);
            mma_bf16(av[2*p],   aH, bH[0], bH[1]);
            mma_bf16(av[2*p+1], aH, bH[2], bH[3]);
            mma_bf16(av[2*p],   aH, bL[0], bL[1]);
            mma_bf16(av[2*p+1], aH, bL[2], bL[3]);
            mma_bf16(av[2*p],   aL, bH[0], bH[1]);
            mma_bf16(av[2*p+1], aL, bH[2], bH[3]);
        }
    }

    // ---- combine warp-pair partials; direct fp16 store ----
    if (wn == 1) {
        #pragma unroll
        for (int nt = 0; nt < 8; nt++) {
            int c0 = 8 * nt + 2 * (lane & 3);
            po[rA * POSTR + c0]     = av[nt][0];
            po[rA * POSTR + c0 + 1] = av[nt][1];
            po[rB * POSTR + c0]     = av[nt][2];
            po[rB * POSTR + c0 + 1] = av[nt][3];
        }
    }
    __syncthreads();
    if (wn == 0) {
        size_t orowA = ((size_t)((Bq * NHASH + nh) * TLEN + tiA)) * E;
        size_t orowB = ((size_t)((Bq * NHASH + nh) * TLEN + tiB)) * E;
        #pragma unroll
        for (int nt = 0; nt < 8; nt++) {
            int c0 = 8 * nt + 2 * (lane & 3);
            float o0 = (av[nt][0] + po[rA * POSTR + c0])     * invsA;
            float o1 = (av[nt][1] + po[rA * POSTR + c0 + 1]) * invsA;
            float o2 = (av[nt][2] + po[rB * POSTR + c0])     * invsB;
            float o3 = (av[nt][3] + po[rB * POSTR + c0 + 1]) * invsB;
            __half2 hA = __floats2half2_rn(o0, o1);
            __half2 hB = __floats2half2_rn(o2, o3);
            *(u32*)&g_o[orowA + c0] = *(u32*)&hA;
            *(u32*)&g_o[orowB + c0] = *(u32*)&hB;
        }
        if ((lane & 3) == 0) {
            g_logits[(Bq * NHASH + nh) * TLEN + tiA] = lseA;
            g_logits[(Bq * NHASH + nh) * TLEN + tiB] = lseB;
        }
    }
}

// ---------------- combine (R10 exact) ----------------
__global__ void combine_kernel(float* __restrict__ out) {
    int gid = blockIdx.x * blockDim.x + threadIdx.x;
    int d4 = (gid & 15) << 2;
    int token = gid >> 4;
    int B = token >> 12, t = token & (TLEN - 1);

    float l[NHASH];
    float mx = -INFINITY;
    #pragma unroll
    for (int nh = 0; nh < NHASH; nh++) {
        l[nh] = g_logits[(B * NHASH + nh) * TLEN + t];
        mx = fmaxf(mx, l[nh]);
    }
    float s = 0.f;
    #pragma unroll
    for (int nh = 0; nh < NHASH; nh++) { l[nh] = __expf(l[nh] - mx); s += l[nh]; }
    float inv = 1.f / s;
    float4 acc = make_float4(0.f, 0.f, 0.f, 0.f);
    #pragma unroll
    for (int nh = 0; nh < NHASH; nh++) {
        float wgt = l[nh] * inv;
        uint2 raw = *(const uint2*)&g_o[((size_t)((B * NHASH + nh) * TLEN + t)) * E + d4];
        float2 f01 = __half22float2(*(__half2*)&raw.x);
        float2 f23 = __half22float2(*(__half2*)&raw.y);
        acc.x = fmaf(wgt, f01.x, acc.x);
        acc.y = fmaf(wgt, f01.y, acc.y);
        acc.z = fmaf(wgt, f23.x, acc.z);
        acc.w = fmaf(wgt, f23.y, acc.w);
    }
    *(float4*)&out[((size_t)token) * E + d4] = acc;
}

extern "C" void kernel_launch(void* const* d_in, const int* in_sizes, int n_in,
                              void* d_out, int out_size) {
    const float* qk  = (const float*)d_in[0];
    // d_in[1] = k is unused by the reference (shared-QK attention)
    const float* v   = (const float*)d_in[2];
    const float* rot = (const float*)d_in[3];
    float* out = (float*)d_out;

    const int hash_smem = (256 * STR + 64 * STR) * (int)sizeof(float);
    cudaFuncSetAttribute(attn_kernel, cudaFuncAttributeMaxDynamicSharedMemorySize, ATTN_SMEM);
    cudaFuncSetAttribute(hash_kernel, cudaFuncAttributeMaxDynamicSharedMemorySize, hash_smem);

    cudaStream_t s2 = 0;
    cudaEvent_t eF = 0, eJ = 0;
    bool forked = false;
    {
        cudaStream_t tmp;
        if (cudaStreamCreateWithFlags(&tmp, cudaStreamNonBlocking) == cudaSuccess) {
            if (cudaEventCreateWithFlags(&eF, cudaEventDisableTiming) == cudaSuccess &&
                cudaEventCreateWithFlags(&eJ, cudaEventDisableTiming) == cudaSuccess) {
                s2 = tmp;
                forked = true;
            }
        }
    }
    cudaStream_t sB = forked ? s2 : (cudaStream_t)0;

    zero_counts_kernel<<<32, 256, 0, 0>>>(0);   // zeros ALL NB*NGBUCK counters
    if (forked) {
        cudaEventRecord(eF, 0);
        cudaStreamWaitEvent(s2, eF, 0);
    }

    hash_kernel   <<<(NB / 2) * 64,     256, hash_smem, 0 >>>(qk, rot, 0);
    hash_kernel   <<<(NB / 2) * 64,     256, hash_smem, sB>>>(qk, rot, NB / 2);
    scan_kernel   <<<NB / 2,            NGBUCK, 0,      0 >>>(0);
    scatter_kernel<<<(NB / 2) * NHASH,  256, 0,         0 >>>(0);
    attn_kernel   <<<(NB / 2) * CHUNKS, 256, ATTN_SMEM, 0 >>>(qk, v, 0);
    scan_kernel   <<<NB / 2,            NGBUCK, 0,      sB>>>(NB / 2);
    scatter_kernel<<<(NB / 2) * NHASH,  256, 0,         sB>>>(NB / 2);
    attn_kernel   <<<(NB / 2) * CHUNKS, 256, ATTN_SMEM, sB>>>(qk, v, NB / 2);

    if (forked) {
        cudaEventRecord(eJ, s2);
        cudaStreamWaitEvent(0, eJ, 0);
    }
    combine_kernel<<<NB * TLEN * E / 4 / 256, 256>>>(out);
}

// round 17
// speedup vs baseline: 1.5325x; 1.0240x over previous
#include <cuda_runtime.h>
#include <cuda_bf16.h>
#include <cuda_fp16.h>
#include <stdint.h>
#include <cstdint>
#include <math.h>

// Problem constants
#define NB 16        // B = b*h
#define TLEN 4096    // sequence length
#define NHASH 8
#define NBUCK 64     // local buckets per round
#define NGBUCK 512   // global buckets per B-row
#define CHUNKS 512   // chunks per B-row
#define CS 64        // chunk size
#define E 64         // head dim
#define STR 68       // smem row stride (floats) for hash kernel

typedef unsigned int u32;

// Scratch (device globals — no allocations allowed).
// g_counts is zero-initialized at module load and RESET by scan_kernel after
// each read, so it is zero at the entry of every kernel_launch invocation.
__device__ unsigned char g_buckets[NB * NHASH * TLEN];
__device__ int    g_counts [NB * NGBUCK];
__device__ int    g_offsets[NB * NGBUCK];
__device__ int    g_st     [NB * NHASH * TLEN];
__device__ float  g_logits [NB * NHASH * TLEN];
__device__ __half g_o      [(size_t)NB * NHASH * TLEN * E];   // 64MB (fp16 per-round outputs)

// ---------------- hash: 4 hash rounds x 8 tokens per accumulator pass (R15 exact) ----------------
__global__ void __launch_bounds__(256, 2) hash_kernel(const float* __restrict__ qk,
                                                      const float* __restrict__ rot,
                                                      int Boff) {
    extern __shared__ float hsm[];
    float* srot = hsm;               // 256 rows x STR
    float* sq   = srot + 256 * STR;  // 64 tokens x STR

    int tid = threadIdx.x;
    int B  = (blockIdx.x >> 6) + Boff;
    int t0 = (blockIdx.x & 63) << 6;
    int b = B >> 3, hh = B & 7;

    for (int idx = tid; idx < 64 * NHASH * 32; idx += 256) {
        int e = idx >> 8, r = idx & 255;
        srot[r * STR + e] = rot[idx];
    }
    for (int idx = tid; idx < 64 * 16; idx += 256) {
        int tok = idx >> 4, e4 = (idx & 15) << 2;
        const float* q = qk + (((size_t)(b * TLEN + t0 + tok)) * 8 + hh) * E;
        *(float4*)&sq[tok * STR + e4] = *(const float4*)&q[e4];
    }
    __syncthreads();

    int w = tid >> 5, lane = tid & 31;
    int r0 = w * 8;

    #pragma unroll
    for (int nhp = 0; nhp < NHASH; nhp += 4) {
        float acc[4][8];
        #pragma unroll
        for (int hq = 0; hq < 4; hq++)
            #pragma unroll
            for (int r = 0; r < 8; r++) acc[hq][r] = 0.f;

        #pragma unroll 4
        for (int e4 = 0; e4 < 64; e4 += 4) {
            float4 rv0 = *(const float4*)&srot[((nhp + 0) * 32 + lane) * STR + e4];
            float4 rv1 = *(const float4*)&srot[((nhp + 1) * 32 + lane) * STR + e4];
            float4 rv2 = *(const float4*)&srot[((nhp + 2) * 32 + lane) * STR + e4];
            float4 rv3 = *(const float4*)&srot[((nhp + 3) * 32 + lane) * STR + e4];
            #pragma unroll
            for (int r = 0; r < 8; r++) {
                float4 qv = *(const float4*)&sq[(r0 + r) * STR + e4];
                acc[0][r] = fmaf(qv.x, rv0.x, fmaf(qv.y, rv0.y, fmaf(qv.z, rv0.z, fmaf(qv.w, rv0.w, acc[0][r]))));
                acc[1][r] = fmaf(qv.x, rv1.x, fmaf(qv.y, rv1.y, fmaf(qv.z, rv1.z, fmaf(qv.w, rv1.w, acc[1][r]))));
                acc[2][r] = fmaf(qv.x, rv2.x, fmaf(qv.y, rv2.y, fmaf(qv.z, rv2.z, fmaf(qv.w, rv2.w, acc[2][r]))));
                acc[3][r] = fmaf(qv.x, rv3.x, fmaf(qv.y, rv3.y, fmaf(qv.z, rv3.z, fmaf(qv.w, rv3.w, acc[3][r]))));
            }
        }

        #pragma unroll
        for (int hq = 0; hq < 4; hq++) {
            int nh = nhp + hq;
            #pragma unroll
            for (int r = 0; r < 8; r++) {
                float a = acc[hq][r];
                float bestv; int besti;
                if (-a > a) { bestv = -a; besti = lane + 32; }
                else        { bestv =  a; besti = lane; }
                #pragma unroll
                for (int off = 16; off; off >>= 1) {
                    float ov = __shfl_down_sync(0xffffffffu, bestv, off);
                    int   oi = __shfl_down_sync(0xffffffffu, besti, off);
                    if (ov > bestv || (ov == bestv && oi < besti)) { bestv = ov; besti = oi; }
                }
                besti = __shfl_sync(0xffffffffu, besti, 0);
                if (lane == 0) {
                    int t = t0 + r0 + r;
                    g_buckets[(B * NHASH + nh) * TLEN + t] = (unsigned char)besti;
                    atomicAdd(&g_counts[B * NGBUCK + nh * NBUCK + besti], 1);
                }
            }
        }
    }
}

// Scan reads counts, then RESETS them to zero (invariant for next replay).
__global__ void scan_kernel(int Boff) {
    __shared__ int s[NGBUCK];
    int B = blockIdx.x + Boff, tid = threadIdx.x;
    s[tid] = g_counts[B * NGBUCK + tid];
    g_counts[B * NGBUCK + tid] = 0;
    __syncthreads();
    for (int off = 1; off < NGBUCK; off <<= 1) {
        int v = (tid >= off) ? s[tid - off] : 0;
        __syncthreads();
        s[tid] += v;
        __syncthreads();
    }
    g_offsets[B * NGBUCK + tid] = tid ? s[tid - 1] : 0;
}

// Stable counting-sort scatter: 256 threads, 16 passes (R10 known-good).
__global__ void scatter_kernel(int Boff) {
    int B = (blockIdx.x >> 3) + Boff, nh = blockIdx.x & 7;
    __shared__ int cnt[NBUCK];
    __shared__ int wcnt[8][NBUCK];
    int tid = threadIdx.x, w = tid >> 5, lane = tid & 31;

    if (tid < NBUCK) cnt[tid] = g_offsets[B * NGBUCK + nh * NBUCK + tid];
    const unsigned char* src = &g_buckets[(B * NHASH + nh) * TLEN];
    int* dst = &g_st[B * (NHASH * TLEN)];

    for (int pass = 0; pass < 16; pass++) {
        wcnt[w][lane] = 0; wcnt[w][lane + 32] = 0;
        __syncthreads();
        int t = pass * 256 + tid;
        int bk = src[t];
        unsigned mask = __match_any_sync(0xffffffffu, bk);
        int rank = __popc(mask & ((1u << lane) - 1u));
        if (rank == 0) wcnt[w][bk] = __popc(mask);
        __syncthreads();
        int pos = cnt[bk] + rank;
        #pragma unroll
        for (int w2 = 0; w2 < 8; w2++)
            if (w2 < w) pos += wcnt[w2][bk];
        dst[pos] = t;
        __syncthreads();
        if (tid < NBUCK) {
            int s = 0;
            #pragma unroll
            for (int w2 = 0; w2 < 8; w2++) s += wcnt[w2][tid];
            cnt[tid] += s;
        }
        __syncthreads();
    }
}

// ---------------- helpers ----------------
__device__ __forceinline__ u32 swz(int row, int chunk) {
    return (u32)(row * 128 + (((chunk ^ (row & 7)) & 7) << 4));
}
__device__ __forceinline__ void ldsm_x4(u32* r, u32 addr) {
    asm volatile("ldmatrix.sync.aligned.m8n8.x4.shared.b16 {%0,%1,%2,%3}, [%4];"
                 : "=r"(r[0]), "=r"(r[1]), "=r"(r[2]), "=r"(r[3]) : "r"(addr));
}
__device__ __forceinline__ void ldsm_x4t(u32* r, u32 addr) {
    asm volatile("ldmatrix.sync.aligned.m8n8.x4.trans.shared.b16 {%0,%1,%2,%3}, [%4];"
                 : "=r"(r[0]), "=r"(r[1]), "=r"(r[2]), "=r"(r[3]) : "r"(addr));
}
__device__ __forceinline__ void mma_bf16(float* d, const u32* a, u32 b0, u32 b1) {
    asm volatile("mma.sync.aligned.m16n8k16.row.col.f32.bf16.bf16.f32 "
                 "{%0,%1,%2,%3},{%4,%5,%6,%7},{%8,%9},{%0,%1,%2,%3};"
                 : "+f"(d[0]), "+f"(d[1]), "+f"(d[2]), "+f"(d[3])
                 : "r"(a[0]), "r"(a[1]), "r"(a[2]), "r"(a[3]), "r"(b0), "r"(b1));
}
__device__ __forceinline__ u32 prmt7632(u32 a, u32 b) {
    u32 r;
    asm("prmt.b32 %0, %1, %2, 0x7632;" : "=r"(r) : "r"(a), "r"(b));
    return r;
}
// Veltkamp truncation split: hi = trunc-bf16(x) (exact residual), lo = bf16(x-hi)
__device__ __forceinline__ void split2(float a, float b, u32& hi, u32& lo) {
    u32 ua = __float_as_uint(a) & 0xFFFF0000u;
    u32 ub = __float_as_uint(b) & 0xFFFF0000u;
    hi = prmt7632(ua, ub);
    float la = a - __uint_as_float(ua);
    float lb = b - __uint_as_float(ub);
    lo = prmt7632(__float_as_uint(la), __float_as_uint(lb));
}
__device__ __forceinline__ void split8v(const float* x, uint4& hi, uint4& lo) {
    u32 h[4], l[4];
    #pragma unroll
    for (int p = 0; p < 4; p++) split2(x[2*p], x[2*p+1], h[p], l[p]);
    hi = make_uint4(h[0], h[1], h[2], h[3]);
    lo = make_uint4(l[0], l[1], l[2], l[3]);
}

// ---------------- tensor-core attention (R10/R14 exact) ----------------
#define SM_KLO 16384
#define SM_VHI 32768
#define SM_VLO 49152
#define SM_PO  65536
#define SM_INV 82944
#define SM_RDS 83456
#define SM_STK 83968
#define ATTN_SMEM 84480
#define POSTR 68

__global__ void __launch_bounds__(256, 2) attn_kernel(const float* __restrict__ qk,
                                                      const float* __restrict__ vv,
                                                      int Boff) {
    extern __shared__ char smem[];
    float* po   = (float*)(smem + SM_PO);
    float* invn = (float*)(smem + SM_INV);
    float* reds = (float*)(smem + SM_RDS);
    int*   stk  = (int*)  (smem + SM_STK);

    int tid = threadIdx.x;
    int Bq = (blockIdx.x >> 9) + Boff;
    int c  = blockIdx.x & (CHUNKS - 1);
    int cp = (c + CHUNKS - 1) & (CHUNKS - 1);
    int b = Bq >> 3, hh = Bq & 7;
    int nh = c >> 6;

    if (tid < 128) {
        int p = (tid < 64) ? (c * CS + tid) : (cp * CS + tid - 64);
        stk[tid] = g_st[Bq * (NHASH * TLEN) + p];
    }
    __syncthreads();

    // ---- gather (L2-resident inputs) + truncation split + key norms ----
    {
        int seg = tid & 7;              // 8-col segment of a row
        #pragma unroll
        for (int pass = 0; pass < 4; pass++) {
            int j = (tid >> 3) + pass * 32;
            size_t base = (((size_t)(b * TLEN + stk[j])) * 8 + hh) * E + seg * 8;
            float x[8], y[8];
            *(float4*)&x[0] = *(const float4*)&qk[base];
            *(float4*)&x[4] = *(const float4*)&qk[base + 4];
            *(float4*)&y[0] = *(const float4*)&vv[base];
            *(float4*)&y[4] = *(const float4*)&vv[base + 4];
            u32 off = swz(j, seg);

            uint4 hi, lo;
            split8v(x, hi, lo);
            *(uint4*)(smem + off)          = hi;
            *(uint4*)(smem + SM_KLO + off) = lo;
            split8v(y, hi, lo);
            *(uint4*)(smem + SM_VHI + off) = hi;
            *(uint4*)(smem + SM_VLO + off) = lo;

            float ss = 0.f;
            #pragma unroll
            for (int i = 0; i < 8; i++) ss = fmaf(x[i], x[i], ss);
            ss += __shfl_xor_sync(0xffffffffu, ss, 1);
            ss += __shfl_xor_sync(0xffffffffu, ss, 2);
            ss += __shfl_xor_sync(0xffffffffu, ss, 4);
            if (seg == 0) invn[j] = 1.f / fmaxf(sqrtf(ss), 1e-12f);
        }
    }
    __syncthreads();

    int w = tid >> 5, lane = tid & 31;
    int wm = w & 3, wn = w >> 2;
    int m0 = wm * 16, n0 = wn * 64;
    int g  = lane >> 3, lr = lane & 7;
    u32 kb = (u32)__cvta_generic_to_shared(smem);

    // ---- QK: D[64q,128k] via 3 split MMAs ----
    float acc[8][4];
    #pragma unroll
    for (int nt = 0; nt < 8; nt++) { acc[nt][0]=0.f; acc[nt][1]=0.f; acc[nt][2]=0.f; acc[nt][3]=0.f; }

    #pragma unroll
    for (int ck = 0; ck < 4; ck++) {
        int arow = m0 + ((g & 1) << 3) + lr;
        u32 aoff = swz(arow, 2 * ck + (g >> 1));
        u32 aH[4], aL[4];
        ldsm_x4(aH, kb + aoff);
        ldsm_x4(aL, kb + SM_KLO + aoff);
        #pragma unroll
        for (int p = 0; p < 4; p++) {
            int brow = n0 + 16 * p + ((g >> 1) << 3) + lr;
            u32 boff = swz(brow, 2 * ck + (g & 1));
            u32 bH[4], bL[4];
            ldsm_x4(bH, kb + boff);
            ldsm_x4(bL, kb + SM_KLO + boff);
            mma_bf16(acc[2*p],   aH, bH[0], bH[1]);
            mma_bf16(acc[2*p+1], aH, bH[2], bH[3]);
            mma_bf16(acc[2*p],   aH, bL[0], bL[1]);
            mma_bf16(acc[2*p+1], aH, bL[2], bL[3]);
            mma_bf16(acc[2*p],   aL, bH[0], bH[1]);
            mma_bf16(acc[2*p+1], aL, bH[2], bH[3]);
        }
    }

    // ---- scale by key inv-norm, self-mask, bound-max softmax ----
    int rA = m0 + (lane >> 2), rB = rA + 8;
    int tiA = stk[rA], tiB = stk[rB];
    float mA = 1.0f / invn[rA];
    float mB = 1.0f / invn[rB];

    float sA = 0.f, sB = 0.f;
    #pragma unroll
    for (int nt = 0; nt < 8; nt++) {
        int c0 = n0 + 8 * nt + 2 * (lane & 3);
        float i0 = invn[c0], i1 = invn[c0 + 1];
        int tc0 = stk[c0], tc1 = stk[c0 + 1];
        float d0 = acc[nt][0] * i0, d1 = acc[nt][1] * i1;
        float d2 = acc[nt][2] * i0, d3 = acc[nt][3] * i1;
        if (tc0 == tiA) d0 = -50000.f;
        if (tc1 == tiA) d1 = -50000.f;
        if (tc0 == tiB) d2 = -50000.f;
        if (tc1 == tiB) d3 = -50000.f;
        acc[nt][0] = __expf(d0 - mA);
        acc[nt][1] = __expf(d1 - mA);
        acc[nt][2] = __expf(d2 - mB);
        acc[nt][3] = __expf(d3 - mB);
        sA += acc[nt][0] + acc[nt][1];
        sB += acc[nt][2] + acc[nt][3];
    }
    sA += __shfl_xor_sync(0xffffffffu, sA, 1);
    sA += __shfl_xor_sync(0xffffffffu, sA, 2);
    sB += __shfl_xor_sync(0xffffffffu, sB, 1);
    sB += __shfl_xor_sync(0xffffffffu, sB, 2);

    int ridx = (wm * 2 + wn) * 16 + (lane >> 2);
    int pidx = (wm * 2 + (1 - wn)) * 16 + (lane >> 2);
    if ((lane & 3) == 0) { reds[ridx] = sA; reds[ridx + 8] = sB; }
    __syncthreads();
    sA += reds[pidx]; sB += reds[pidx + 8];
    float invsA = 1.f / sA, invsB = 1.f / sB;
    float lseA = mA + __logf(sA), lseB = mB + __logf(sB);

    // ---- P -> bf16 hi/lo fragments via truncation split ----
    u32 phA[8], phB[8], plA[8], plB[8];
    #pragma unroll
    for (int nt = 0; nt < 8; nt++) {
        split2(acc[nt][0], acc[nt][1], phA[nt], plA[nt]);
        split2(acc[nt][2], acc[nt][3], phB[nt], plB[nt]);
    }

    // ---- PV: out[64q,64d] partials over this warp's 64 j's ----
    float av[8][4];
    #pragma unroll
    for (int nt = 0; nt < 8; nt++) { av[nt][0]=0.f; av[nt][1]=0.f; av[nt][2]=0.f; av[nt][3]=0.f; }

    #pragma unroll
    for (int k = 0; k < 4; k++) {
        u32 aH[4] = { phA[2*k], phB[2*k], phA[2*k+1], phB[2*k+1] };
        u32 aL[4] = { plA[2*k], plB[2*k], plA[2*k+1], plB[2*k+1] };
        int vrow = n0 + 16 * k + ((g & 1) << 3) + lr;
        #pragma unroll
        for (int p = 0; p < 4; p++) {
            u32 voff = swz(vrow, 2 * p + (g >> 1));
            u32 bH[4], bL[4];
            ldsm_x4t(bH, kb + SM_VHI + voff);
            ldsm_x4t(bL, kb + SM_VLO + voff);
            mma_bf16(av[2*p],   aH, bH[0], bH[1]);
            mma_bf16(av[2*p+1], aH, bH[2], bH[3]);
            mma_bf16(av[2*p],   aH, bL[0], bL[1]);
            mma_bf16(av[2*p+1], aH, bL[2], bL[3]);
            mma_bf16(av[2*p],   aL, bH[0], bH[1]);
            mma_bf16(av[2*p+1], aL, bH[2], bH[3]);
        }
    }

    // ---- combine warp-pair partials; direct fp16 store ----
    if (wn == 1) {
        #pragma unroll
        for (int nt = 0; nt < 8; nt++) {
            int c0 = 8 * nt + 2 * (lane & 3);
            po[rA * POSTR + c0]     = av[nt][0];
            po[rA * POSTR + c0 + 1] = av[nt][1];
            po[rB * POSTR + c0]     = av[nt][2];
            po[rB * POSTR + c0 + 1] = av[nt][3];
        }
    }
    __syncthreads();
    if (wn == 0) {
        size_t orowA = ((size_t)((Bq * NHASH + nh) * TLEN + tiA)) * E;
        size_t orowB = ((size_t)((Bq * NHASH + nh) * TLEN + tiB)) * E;
        #pragma unroll
        for (int nt = 0; nt < 8; nt++) {
            int c0 = 8 * nt + 2 * (lane & 3);
            float o0 = (av[nt][0] + po[rA * POSTR + c0])     * invsA;
            float o1 = (av[nt][1] + po[rA * POSTR + c0 + 1]) * invsA;
            float o2 = (av[nt][2] + po[rB * POSTR + c0])     * invsB;
            float o3 = (av[nt][3] + po[rB * POSTR + c0 + 1]) * invsB;
            __half2 hA = __floats2half2_rn(o0, o1);
            __half2 hB = __floats2half2_rn(o2, o3);
            *(u32*)&g_o[orowA + c0] = *(u32*)&hA;
            *(u32*)&g_o[orowB + c0] = *(u32*)&hB;
        }
        if ((lane & 3) == 0) {
            g_logits[(Bq * NHASH + nh) * TLEN + tiA] = lseA;
            g_logits[(Bq * NHASH + nh) * TLEN + tiB] = lseB;
        }
    }
}

// ---------------- combine: per-half (Boff), runs on each chain's own stream ----------------
__global__ void combine_kernel(float* __restrict__ out, int Boff) {
    int gid = blockIdx.x * blockDim.x + threadIdx.x;   // (NB/2)*TLEN*16 threads
    int d4 = (gid & 15) << 2;
    int token = Boff * TLEN + (gid >> 4);
    int B = token >> 12, t = token & (TLEN - 1);

    float l[NHASH];
    float mx = -INFINITY;
    #pragma unroll
    for (int nh = 0; nh < NHASH; nh++) {
        l[nh] = g_logits[(B * NHASH + nh) * TLEN + t];
        mx = fmaxf(mx, l[nh]);
    }
    float s = 0.f;
    #pragma unroll
    for (int nh = 0; nh < NHASH; nh++) { l[nh] = __expf(l[nh] - mx); s += l[nh]; }
    float inv = 1.f / s;
    float4 acc = make_float4(0.f, 0.f, 0.f, 0.f);
    #pragma unroll
    for (int nh = 0; nh < NHASH; nh++) {
        float wgt = l[nh] * inv;
        uint2 raw = *(const uint2*)&g_o[((size_t)((B * NHASH + nh) * TLEN + t)) * E + d4];
        float2 f01 = __half22float2(*(__half2*)&raw.x);
        float2 f23 = __half22float2(*(__half2*)&raw.y);
        acc.x = fmaf(wgt, f01.x, acc.x);
        acc.y = fmaf(wgt, f01.y, acc.y);
        acc.z = fmaf(wgt, f23.x, acc.z);
        acc.w = fmaf(wgt, f23.y, acc.w);
    }
    *(float4*)&out[((size_t)token) * E + d4] = acc;
}

extern "C" void kernel_launch(void* const* d_in, const int* in_sizes, int n_in,
                              void* d_out, int out_size) {
    const float* qk  = (const float*)d_in[0];
    // d_in[1] = k is unused by the reference (shared-QK attention)
    const float* v   = (const float*)d_in[2];
    const float* rot = (const float*)d_in[3];
    float* out = (float*)d_out;

    const int hash_smem = (256 * STR + 64 * STR) * (int)sizeof(float);
    cudaFuncSetAttribute(attn_kernel, cudaFuncAttributeMaxDynamicSharedMemorySize, ATTN_SMEM);
    cudaFuncSetAttribute(hash_kernel, cudaFuncAttributeMaxDynamicSharedMemorySize, hash_smem);

    // Proven 1-side-stream + 2-event fork/join pattern (capture-safe, no alloc drift).
    cudaStream_t s2 = 0;
    cudaEvent_t eF = 0, eJ = 0;
    bool forked = false;
    {
        cudaStream_t tmp;
        if (cudaStreamCreateWithFlags(&tmp, cudaStreamNonBlocking) == cudaSuccess) {
            if (cudaEventCreateWithFlags(&eF, cudaEventDisableTiming) == cudaSuccess &&
                cudaEventCreateWithFlags(&eJ, cudaEventDisableTiming) == cudaSuccess) {
                s2 = tmp;
                forked = true;
            }
        }
    }
    cudaStream_t sB = forked ? s2 : (cudaStream_t)0;

    // Fork immediately: counts are already zero (zeroinit + scan resets).
    if (forked) {
        cudaEventRecord(eF, 0);
        cudaStreamWaitEvent(s2, eF, 0);
    }

    const int HB = NB / 2;
    // Half A chain (legacy stream) — includes its own combine.
    hash_kernel   <<<HB * 64,            256, hash_smem, 0 >>>(qk, rot, 0);
    // Half B chain (side stream)
    hash_kernel   <<<HB * 64,            256, hash_smem, sB>>>(qk, rot, HB);
    scan_kernel   <<<HB,                 NGBUCK, 0,      0 >>>(0);
    scatter_kernel<<<HB * NHASH,         256, 0,         0 >>>(0);
    attn_kernel   <<<HB * CHUNKS,        256, ATTN_SMEM, 0 >>>(qk, v, 0);
    combine_kernel<<<HB * TLEN * 16/256, 256, 0,         0 >>>(out, 0);
    scan_kernel   <<<HB,                 NGBUCK, 0,      sB>>>(HB);
    scatter_kernel<<<HB * NHASH,         256, 0,         sB>>>(HB);
    attn_kernel   <<<HB * CHUNKS,        256, ATTN_SMEM, sB>>>(qk, v, HB);
    combine_kernel<<<HB * TLEN * 16/256, 256, 0,         sB>>>(out, HB);

    if (forked) {
        cudaEventRecord(eJ, s2);
        cudaStreamWaitEvent(0, eJ, 0);
    }
}